// round 11
// baseline (speedup 1.0000x reference)
#include <cuda_runtime.h>

// WindowAttention fused kernel, fp32 packed fma.rn.f32x2 (sm_103a).
// R10: square 8x8 thread tiles with split-K/J/M + smem partial reduction;
//      proj_w staging overlapped with GEMM3; v_t row-rotated (LDV2=80).

#define SCALE_F 0.17677669529663687f   // 32^-0.5

#define LDN  68    // k-major [*][64(+4 swizzle)] arrays (float4-aligned rows)
#define LDV2 80    // v_t stride (swizzle + row rotation head-room)
#define LDW  260   // staged qkv_w chunk [16][256] padded
#define LDP  132   // p_t rows [*][128] padded

#define SW(c)  ((c) + (((c) & 32) >> 3))
#define ROT(r) (((r) & 24) >> 1)

#define OFF_QT 0                        // q_t -> o_t [128][LDN]
#define OFF_KT (128*LDN)                // k_t [128][LDN] -> p_t_lo [64][LDP]
#define OFF_V  (2*128*LDN)              // v_t [128][LDV2] -> GEMM4 scratch [128][LDN]
#define OFF_AT (OFF_V + 128*LDV2)       // y_t/attn_t [256][LDN] -> p_t_hi [64][LDP]
#define OFF_W  (OFF_AT + 128*LDN)       // W buffers: 2 x [16][LDW] (upper AT half)
#define OFF_SC (OFF_AT + 256*LDN)       // softmax scratch [2][256]
#define SMEM_FLOATS (OFF_SC + 512)
#define SMEM_BYTES  (SMEM_FLOATS * 4)   // 182272 B

typedef unsigned long long u64;

__device__ __forceinline__ u64 pk2(float v) {
    u64 r; asm("mov.b64 %0, {%1, %1};" : "=l"(r) : "f"(v)); return r;
}
__device__ __forceinline__ u64 pkab(float lo, float hi) {
    u64 r; asm("mov.b64 %0, {%1, %2};" : "=l"(r) : "f"(lo), "f"(hi)); return r;
}
__device__ __forceinline__ u64 f2fma(u64 a, u64 b, u64 c) {
    u64 d; asm("fma.rn.f32x2 %0, %1, %2, %3;" : "=l"(d) : "l"(a), "l"(b), "l"(c)); return d;
}
__device__ __forceinline__ u64 f2add(u64 a, u64 b) {
    u64 d; asm("add.rn.f32x2 %0, %1, %2;" : "=l"(d) : "l"(a), "l"(b)); return d;
}
__device__ __forceinline__ void upk2(u64 v, float& lo, float& hi) {
    asm("mov.b64 {%0, %1}, %2;" : "=f"(lo), "=f"(hi) : "l"(v));
}
__device__ __forceinline__ u64 lds2(const float* p) {
    return *reinterpret_cast<const u64*>(p);
}
__device__ __forceinline__ void gbar(int id) {
    asm volatile("bar.sync %0, 256;" :: "r"(id) : "memory");
}

__global__ void __launch_bounds__(512, 1)
wattn_kernel(const float* __restrict__ x, const float* __restrict__ y,
             const float* __restrict__ P, const float* __restrict__ maskp,
             const float* __restrict__ qkv_w, const float* __restrict__ qkv_b,
             const float* __restrict__ proj_w, const float* __restrict__ proj_b,
             const float* __restrict__ lam_p, float* __restrict__ out)
{
    extern __shared__ float sm[];
    const int b   = blockIdx.x;
    const int tid = threadIdx.x;

    // ===== Phase 0: register 4x4 block transposes =====
    {
        const int h = tid >> 7, nb = (tid >> 3) & 15, db = tid & 7;
        const float* xb = x + (size_t)b * 8192 + h * 2048 + db * 4;
        float4 r0 = *(const float4*)(xb + (4 * nb + 0) * 32);
        float4 r1 = *(const float4*)(xb + (4 * nb + 1) * 32);
        float4 r2 = *(const float4*)(xb + (4 * nb + 2) * 32);
        float4 r3 = *(const float4*)(xb + (4 * nb + 3) * 32);
        float* qb = &sm[OFF_QT + (32 * h + 4 * db) * LDN + SW(4 * nb)];
        *(float4*)(qb + 0 * LDN) = make_float4(r0.x*SCALE_F, r1.x*SCALE_F, r2.x*SCALE_F, r3.x*SCALE_F);
        *(float4*)(qb + 1 * LDN) = make_float4(r0.y*SCALE_F, r1.y*SCALE_F, r2.y*SCALE_F, r3.y*SCALE_F);
        *(float4*)(qb + 2 * LDN) = make_float4(r0.z*SCALE_F, r1.z*SCALE_F, r2.z*SCALE_F, r3.z*SCALE_F);
        *(float4*)(qb + 3 * LDN) = make_float4(r0.w*SCALE_F, r1.w*SCALE_F, r2.w*SCALE_F, r3.w*SCALE_F);
    }
    {
        const int nb = tid & 15, kb = tid >> 4;       // kb 0..31
        const float* yb = y + (size_t)b * 8192 + kb * 4;
        float4 r0 = *(const float4*)(yb + (4 * nb + 0) * 128);
        float4 r1 = *(const float4*)(yb + (4 * nb + 1) * 128);
        float4 r2 = *(const float4*)(yb + (4 * nb + 2) * 128);
        float4 r3 = *(const float4*)(yb + (4 * nb + 3) * 128);
        float* yt = &sm[OFF_AT + (4 * kb) * LDN + SW(4 * nb)];
        *(float4*)(yt + 0 * LDN) = make_float4(r0.x, r1.x, r2.x, r3.x);
        *(float4*)(yt + 1 * LDN) = make_float4(r0.y, r1.y, r2.y, r3.y);
        *(float4*)(yt + 2 * LDN) = make_float4(r0.z, r1.z, r2.z, r3.z);
        *(float4*)(yt + 3 * LDN) = make_float4(r0.w, r1.w, r2.w, r3.w);
    }

    // ===== GEMM1: kv[n][c] = sum_k y_t[k][n]*qkv_w[c][k] + qkv_b[c] =====
    // 2-way split-k, 8n x 8c tiles, group-local barriers for weight staging.
    {
        const int g = tid >> 8, gtid = tid & 255;
        const int tc = gtid >> 3, tr = gtid & 7;
        const int c0 = tc << 3, r0 = tr << 3, r0s = SW(r0);
        const int kbase = g << 6;
        const int WB = OFF_W + g * (16 * LDW);
        const int barid = 1 + g;
        const float* wsrc = qkv_w + gtid * 128 + kbase;

        u64 acc[4][8];
        #pragma unroll
        for (int p = 0; p < 4; ++p)
            #pragma unroll
            for (int cc = 0; cc < 8; ++cc) acc[p][cc] = 0ull;

        {   // stage chunk 0 (column gtid, 16 k values)
            float4 pw0 = *(const float4*)(wsrc);
            float4 pw1 = *(const float4*)(wsrc + 4);
            float4 pw2 = *(const float4*)(wsrc + 8);
            float4 pw3 = *(const float4*)(wsrc + 12);
            float wv[16] = {pw0.x,pw0.y,pw0.z,pw0.w, pw1.x,pw1.y,pw1.z,pw1.w,
                            pw2.x,pw2.y,pw2.z,pw2.w, pw3.x,pw3.y,pw3.z,pw3.w};
            #pragma unroll
            for (int jj = 0; jj < 16; ++jj)
                sm[WB + jj * LDW + gtid] = wv[jj];
        }
        __syncthreads();   // y_t/q_t + both W chunk0 buffers visible

        #pragma unroll 1
        for (int ch = 0; ch < 4; ++ch) {
            const int kk = kbase + (ch << 4);
            float4 pw0, pw1, pw2, pw3;
            if (ch < 3) {
                const float* ws = wsrc + ((ch + 1) << 4);
                pw0 = *(const float4*)(ws);
                pw1 = *(const float4*)(ws + 4);
                pw2 = *(const float4*)(ws + 8);
                pw3 = *(const float4*)(ws + 12);
            }
            #pragma unroll 8
            for (int j = 0; j < 16; ++j) {
                const float* ar = &sm[OFF_AT + (kk + j) * LDN + r0s];
                float4 af0 = *(const float4*)ar;
                float4 af1 = *(const float4*)(ar + 4);
                u64 a0 = pkab(af0.x, af0.y), a1 = pkab(af0.z, af0.w);
                u64 a2 = pkab(af1.x, af1.y), a3 = pkab(af1.z, af1.w);
                const float* br = &sm[WB + j * LDW + c0];
                float4 bv0 = *(const float4*)br;
                float4 bv1 = *(const float4*)(br + 4);
                float bs[8] = {bv0.x,bv0.y,bv0.z,bv0.w, bv1.x,bv1.y,bv1.z,bv1.w};
                #pragma unroll
                for (int cc = 0; cc < 8; ++cc) {
                    u64 bb = pk2(bs[cc]);
                    acc[0][cc] = f2fma(a0, bb, acc[0][cc]);
                    acc[1][cc] = f2fma(a1, bb, acc[1][cc]);
                    acc[2][cc] = f2fma(a2, bb, acc[2][cc]);
                    acc[3][cc] = f2fma(a3, bb, acc[3][cc]);
                }
            }
            if (ch < 3) {
                gbar(barid);    // group's compute on current buffer done
                float wv[16] = {pw0.x,pw0.y,pw0.z,pw0.w, pw1.x,pw1.y,pw1.z,pw1.w,
                                pw2.x,pw2.y,pw2.z,pw2.w, pw3.x,pw3.y,pw3.z,pw3.w};
                #pragma unroll
                for (int jj = 0; jj < 16; ++jj)
                    sm[WB + jj * LDW + gtid] = wv[jj];
                gbar(barid);    // new chunk visible to group
            }
        }

        // writeback: g0 raw partial -> dest; g1 adds partial + bias -> dest
        if (g == 0) {
            #pragma unroll
            for (int cc = 0; cc < 8; ++cc) {
                const int c = c0 + cc;
                float* dp = (c < 128) ? &sm[OFF_KT + c * LDN + r0s]
                                      : &sm[OFF_V + (c - 128) * LDV2 + ROT(c - 128) + r0s];
                #pragma unroll
                for (int p = 0; p < 4; ++p)
                    *(u64*)(dp + 2 * p) = acc[p][cc];
            }
        }
        __syncthreads();
        if (g == 1) {
            float bias[8];
            *(float4*)&bias[0] = *(const float4*)(qkv_b + c0);
            *(float4*)&bias[4] = *(const float4*)(qkv_b + c0 + 4);
            #pragma unroll
            for (int cc = 0; cc < 8; ++cc) {
                const int c = c0 + cc;
                float* dp = (c < 128) ? &sm[OFF_KT + c * LDN + r0s]
                                      : &sm[OFF_V + (c - 128) * LDV2 + ROT(c - 128) + r0s];
                u64 bb = pk2(bias[cc]);
                #pragma unroll
                for (int p = 0; p < 4; ++p) {
                    u64 part = lds2(dp + 2 * p);
                    *(u64*)(dp + 2 * p) = f2add(f2add(acc[p][cc], part), bb);
                }
            }
        }
    }
    __syncthreads();

    // ===== GEMM2: attn_t[h*64+m][n] = sum_d q_t[32h+d][n]*k_t[32h+d][m] =====
    {
        const int h = tid >> 7, rest = tid & 127;
        const int mg = rest >> 3, tr = rest & 7;
        const int m0 = mg << 2, r0 = tr << 3;
        const int r0s = SW(r0), m0s = SW(m0);
        u64 acc[4][4];
        #pragma unroll
        for (int p = 0; p < 4; ++p)
            #pragma unroll
            for (int cc = 0; cc < 4; ++cc) acc[p][cc] = 0ull;
        #pragma unroll 8
        for (int d = 0; d < 32; ++d) {
            const int row = (h << 5) + d;
            const float* ar = &sm[OFF_QT + row * LDN + r0s];
            float4 af0 = *(const float4*)ar;
            float4 af1 = *(const float4*)(ar + 4);
            u64 a0 = pkab(af0.x, af0.y), a1 = pkab(af0.z, af0.w);
            u64 a2 = pkab(af1.x, af1.y), a3 = pkab(af1.z, af1.w);
            float4 bv = *(const float4*)&sm[OFF_KT + row * LDN + m0s];
            float bs[4] = {bv.x, bv.y, bv.z, bv.w};
            #pragma unroll
            for (int cc = 0; cc < 4; ++cc) {
                u64 bb = pk2(bs[cc]);
                acc[0][cc] = f2fma(a0, bb, acc[0][cc]);
                acc[1][cc] = f2fma(a1, bb, acc[1][cc]);
                acc[2][cc] = f2fma(a2, bb, acc[2][cc]);
                acc[3][cc] = f2fma(a3, bb, acc[3][cc]);
            }
        }
        #pragma unroll
        for (int cc = 0; cc < 4; ++cc) {
            const int row = (h << 6) + m0 + cc;
            #pragma unroll
            for (int p = 0; p < 4; ++p)
                *(u64*)&sm[OFF_AT + row * LDN + r0s + 2 * p] = acc[p][cc];
        }
    }
    __syncthreads();

    // ===== Softmax over m with mask + lambda*P; 2 threads per column =====
    {
        const int col = tid & 255, half = tid >> 8;
        const int h = col >> 6, n = col & 63;
        const int m0 = half << 5;
        const int ns = SW(n);
        const float lam = lam_p[0];
        const int w = b & 2047;
        const float4* Pr = (const float4*)(P + ((((size_t)b * 4 + h) * 64 + n) * 64) + m0);
        const float4* Mr = (const float4*)(maskp + (((size_t)w * 64 + n) * 64) + m0);
        const int base = OFF_AT + ((h << 6) + m0) * LDN + ns;
        float v[32];
        float s = 0.f;
        #pragma unroll
        for (int q = 0; q < 8; ++q) {
            float4 pv = Pr[q];
            float4 mv = Mr[q];
            float t0 = sm[base + (4*q+0)*LDN] + mv.x + lam * pv.x;
            float t1 = sm[base + (4*q+1)*LDN] + mv.y + lam * pv.y;
            float t2 = sm[base + (4*q+2)*LDN] + mv.z + lam * pv.z;
            float t3 = sm[base + (4*q+3)*LDN] + mv.w + lam * pv.w;
            v[4*q+0] = __expf(t0); v[4*q+1] = __expf(t1);
            v[4*q+2] = __expf(t2); v[4*q+3] = __expf(t3);
            s += v[4*q+0] + v[4*q+1] + v[4*q+2] + v[4*q+3];
        }
        sm[OFF_SC + (half << 8) + col] = s;
        __syncthreads();
        const float inv = 1.0f / (sm[OFF_SC + col] + sm[OFF_SC + 256 + col]);
        #pragma unroll
        for (int m = 0; m < 32; ++m) sm[base + m * LDN] = v[m] * inv;
    }
    __syncthreads();

    // ===== Window 1: GEMM3 mainloop (warps 0-7, split-m) || p_t_lo staging (warps 8-15)
    // GEMM3: o_t[j][n] = sum_m attn_t[h*64+m][n] * v_t[j][m], 8n x 8j tiles.
    u64 acc3[4][8];
    int g3 = 0, n0s3 = 0, j03 = 0;
    if (tid < 256) {
        g3 = tid >> 7;
        const int q = tid & 127;
        const int tr = q & 7, jc = q >> 3;
        const int n0 = tr << 3;  n0s3 = SW(n0);
        j03 = jc << 3;
        const int h = jc >> 2;
        const int mbase = g3 << 5;
        #pragma unroll
        for (int p = 0; p < 4; ++p)
            #pragma unroll
            for (int cc = 0; cc < 8; ++cc) acc3[p][cc] = 0ull;
        #pragma unroll 8
        for (int mm = 0; mm < 32; ++mm) {
            const int m = mbase + mm;
            const int ms = SW(m);
            const float* ar = &sm[OFF_AT + ((h << 6) + m) * LDN + n0s3];
            float4 af0 = *(const float4*)ar;
            float4 af1 = *(const float4*)(ar + 4);
            u64 a0 = pkab(af0.x, af0.y), a1 = pkab(af0.z, af0.w);
            u64 a2 = pkab(af1.x, af1.y), a3 = pkab(af1.z, af1.w);
            #pragma unroll
            for (int cc = 0; cc < 8; ++cc) {
                const int vr = j03 + cc;
                u64 bb = pk2(sm[OFF_V + vr * LDV2 + ROT(vr) + ms]);
                acc3[0][cc] = f2fma(a0, bb, acc3[0][cc]);
                acc3[1][cc] = f2fma(a1, bb, acc3[1][cc]);
                acc3[2][cc] = f2fma(a2, bb, acc3[2][cc]);
                acc3[3][cc] = f2fma(a3, bb, acc3[3][cc]);
            }
        }
        if (g3 == 0) {   // raw partial into o_t dest
            #pragma unroll
            for (int cc = 0; cc < 8; ++cc)
                #pragma unroll
                for (int p = 0; p < 4; ++p)
                    *(u64*)&sm[OFF_QT + (j03 + cc) * LDN + n0s3 + 2 * p] = acc3[p][cc];
        }
    } else {
        // stage p_t_lo: p_t[j][c] = proj_w[c][j], j 0..63 -> KT region
        const int s = tid - 256;
        const int c = s >> 1, jh = s & 1;
        const float* pr = proj_w + c * 128 + jh * 32;
        #pragma unroll
        for (int i = 0; i < 8; ++i) {
            float4 pv = ((const float4*)pr)[i];
            const int j = (jh << 5) + (i << 2);
            sm[OFF_KT + (j    ) * LDP + c] = pv.x;
            sm[OFF_KT + (j + 1) * LDP + c] = pv.y;
            sm[OFF_KT + (j + 2) * LDP + c] = pv.z;
            sm[OFF_KT + (j + 3) * LDP + c] = pv.w;
        }
    }
    __syncthreads();

    // ===== Window 2: GEMM3 reduce (warps 4-7) || p_t_hi staging (warps 8-15)
    if (tid < 256) {
        if (g3 == 1) {
            #pragma unroll
            for (int cc = 0; cc < 8; ++cc) {
                float* dp = &sm[OFF_QT + (j03 + cc) * LDN + n0s3];
                #pragma unroll
                for (int p = 0; p < 4; ++p) {
                    u64 part = lds2(dp + 2 * p);
                    *(u64*)(dp + 2 * p) = f2add(acc3[p][cc], part);
                }
            }
        }
    } else {
        // stage p_t_hi: j 64..127 -> AT region (attn dead)
        const int s = tid - 256;
        const int c = s >> 1, jh = s & 1;
        const float* pr = proj_w + c * 128 + 64 + jh * 32;
        #pragma unroll
        for (int i = 0; i < 8; ++i) {
            float4 pv = ((const float4*)pr)[i];
            const int j = (jh << 5) + (i << 2);
            sm[OFF_AT + (j    ) * LDP + c] = pv.x;
            sm[OFF_AT + (j + 1) * LDP + c] = pv.y;
            sm[OFF_AT + (j + 2) * LDP + c] = pv.z;
            sm[OFF_AT + (j + 3) * LDP + c] = pv.w;
        }
    }
    __syncthreads();

    // ===== GEMM4: res[n][c] = sum_j o_t[j][n]*p_t[j][c] + proj_b[c] =====
    // 2-way split-j (warps 0-3: j 0..63 from KT, warps 4-7: j 64..127 from AT).
    u64 acc4[4][8];
    int g4 = 0, n04 = 0, n0s4 = 0, c04 = 0;
    if (tid < 256) {
        g4 = tid >> 7;
        const int q = tid & 127;
        const int tr = q & 7, tc = q >> 3;
        n04 = tr << 3;  n0s4 = SW(n04);  c04 = tc << 3;
        const int jofs = g4 << 6;
        const float* pt = (g4 == 0) ? &sm[OFF_KT] : &sm[OFF_AT];
        #pragma unroll
        for (int p = 0; p < 4; ++p)
            #pragma unroll
            for (int cc = 0; cc < 8; ++cc) acc4[p][cc] = 0ull;
        #pragma unroll 8
        for (int jj = 0; jj < 64; ++jj) {
            const float* ar = &sm[OFF_QT + (jofs + jj) * LDN + n0s4];
            float4 af0 = *(const float4*)ar;
            float4 af1 = *(const float4*)(ar + 4);
            u64 a0 = pkab(af0.x, af0.y), a1 = pkab(af0.z, af0.w);
            u64 a2 = pkab(af1.x, af1.y), a3 = pkab(af1.z, af1.w);
            const float* br = pt + jj * LDP + c04;
            float4 bv0 = *(const float4*)br;
            float4 bv1 = *(const float4*)(br + 4);
            float bs[8] = {bv0.x,bv0.y,bv0.z,bv0.w, bv1.x,bv1.y,bv1.z,bv1.w};
            #pragma unroll
            for (int cc = 0; cc < 8; ++cc) {
                u64 bb = pk2(bs[cc]);
                acc4[0][cc] = f2fma(a0, bb, acc4[0][cc]);
                acc4[1][cc] = f2fma(a1, bb, acc4[1][cc]);
                acc4[2][cc] = f2fma(a2, bb, acc4[2][cc]);
                acc4[3][cc] = f2fma(a3, bb, acc4[3][cc]);
            }
        }
        if (g4 == 1) {   // partial into V scratch [c][n] (v_t dead)
            #pragma unroll
            for (int cc = 0; cc < 8; ++cc)
                #pragma unroll
                for (int p = 0; p < 4; ++p)
                    *(u64*)&sm[OFF_V + (c04 + cc) * LDN + n0s4 + 2 * p] = acc4[p][cc];
        }
    }
    __syncthreads();

    if (tid < 256 && g4 == 0) {
        float bias[8];
        *(float4*)&bias[0] = *(const float4*)(proj_b + c04);
        *(float4*)&bias[4] = *(const float4*)(proj_b + c04 + 4);
        float* ob = out + (size_t)b * 8192;
        #pragma unroll
        for (int p = 0; p < 4; ++p) {
            float lo[8], hi[8];
            #pragma unroll
            for (int cc = 0; cc < 8; ++cc) {
                u64 part = lds2(&sm[OFF_V + (c04 + cc) * LDN + n0s4 + 2 * p]);
                u64 sum = f2add(acc4[p][cc], part);
                float l, h0; upk2(sum, l, h0);
                lo[cc] = l + bias[cc];
                hi[cc] = h0 + bias[cc];
            }
            float* r0p = &ob[(n04 + 2 * p    ) * 128 + c04];
            float* r1p = &ob[(n04 + 2 * p + 1) * 128 + c04];
            *(float4*)(r0p    ) = make_float4(lo[0], lo[1], lo[2], lo[3]);
            *(float4*)(r0p + 4) = make_float4(lo[4], lo[5], lo[6], lo[7]);
            *(float4*)(r1p    ) = make_float4(hi[0], hi[1], hi[2], hi[3]);
            *(float4*)(r1p + 4) = make_float4(hi[4], hi[5], hi[6], hi[7]);
        }
    }
}

extern "C" void kernel_launch(void* const* d_in, const int* in_sizes, int n_in,
                              void* d_out, int out_size)
{
    const float* x      = (const float*)d_in[0];
    const float* y      = (const float*)d_in[1];
    const float* P      = (const float*)d_in[2];
    const float* maskp  = (const float*)d_in[3];
    const float* qkv_w  = (const float*)d_in[4];
    const float* qkv_b  = (const float*)d_in[5];
    const float* proj_w = (const float*)d_in[6];
    const float* proj_b = (const float*)d_in[7];
    const float* lam    = (const float*)d_in[8];
    float* out = (float*)d_out;

    cudaFuncSetAttribute(wattn_kernel,
                         cudaFuncAttributeMaxDynamicSharedMemorySize, SMEM_BYTES);
    wattn_kernel<<<4096, 512, SMEM_BYTES>>>(x, y, P, maskp, qkv_w, qkv_b,
                                            proj_w, proj_b, lam, out);
}

// round 13
// speedup vs baseline: 1.6494x; 1.6494x over previous
#include <cuda_runtime.h>

// WindowAttention fused kernel, fp32 packed fma.rn.f32x2 (sm_103a).
// R11: R9 base (swizzled conflict-free layouts) + clean 2-way split-k GEMM1
//      and split-j GEMM4 (all threads active, uniform addressing).

#define SCALE_F 0.17677669529663687f   // 32^-0.5

#define LDN 68     // k-major [*][64(+4 swizzle)] arrays
#define LDW 260    // staged qkv_w chunk [16][256] padded
#define LDP 132    // p_t [128][128] padded

#define SW(c) ((c) + (((c) & 32) >> 3))

#define OFF_QT 0                        // q_t [128][LDN] -> o_t after GEMM3
#define OFF_KT (128*LDN)                // k_t [128][LDN] (+v_t contiguous below) -> GEMM4 scratch
#define OFF_V  (2*128*LDN)              // v_t [128][LDN]  (k-major [c'][n])
#define OFF_AT (3*128*LDN)              // y_t [128][LDN] -> attn_t [256][LDN] -> p_t [128][LDP]
#define OFF_W  (OFF_AT + 128*LDN)       // W buffers: 2 x [16][LDW] (one per k-group)
#define OFF_SC (OFF_AT + 256*LDN)       // softmax scratch [2][256]
#define SMEM_FLOATS (OFF_SC + 512)
#define SMEM_BYTES  (SMEM_FLOATS * 4)   // 176128 B

typedef unsigned long long u64;

__device__ __forceinline__ u64 pk2(float v) {
    u64 r; asm("mov.b64 %0, {%1, %1};" : "=l"(r) : "f"(v)); return r;
}
__device__ __forceinline__ u64 pkab(float lo, float hi) {
    u64 r; asm("mov.b64 %0, {%1, %2};" : "=l"(r) : "f"(lo), "f"(hi)); return r;
}
__device__ __forceinline__ u64 f2fma(u64 a, u64 b, u64 c) {
    u64 d; asm("fma.rn.f32x2 %0, %1, %2, %3;" : "=l"(d) : "l"(a), "l"(b), "l"(c)); return d;
}
__device__ __forceinline__ u64 f2add(u64 a, u64 b) {
    u64 d; asm("add.rn.f32x2 %0, %1, %2;" : "=l"(d) : "l"(a), "l"(b)); return d;
}
__device__ __forceinline__ void upk2(u64 v, float& lo, float& hi) {
    asm("mov.b64 {%0, %1}, %2;" : "=f"(lo), "=f"(hi) : "l"(v));
}
__device__ __forceinline__ u64 lds2(const float* p) {
    return *reinterpret_cast<const u64*>(p);
}
__device__ __forceinline__ void gbar(int id) {
    asm volatile("bar.sync %0, 256;" :: "r"(id) : "memory");
}

__global__ void __launch_bounds__(512, 1)
wattn_kernel(const float* __restrict__ x, const float* __restrict__ y,
             const float* __restrict__ P, const float* __restrict__ maskp,
             const float* __restrict__ qkv_w, const float* __restrict__ qkv_b,
             const float* __restrict__ proj_w, const float* __restrict__ proj_b,
             const float* __restrict__ lam_p, float* __restrict__ out)
{
    extern __shared__ float sm[];
    const int b   = blockIdx.x;
    const int tid = threadIdx.x;

    // ===== Phase 0: register 4x4 block transposes (swizzled cols) =====
    {
        const int h = tid >> 7, nb = (tid >> 3) & 15, db = tid & 7;
        const float* xb = x + (size_t)b * 8192 + h * 2048 + db * 4;
        float4 r0 = *(const float4*)(xb + (4 * nb + 0) * 32);
        float4 r1 = *(const float4*)(xb + (4 * nb + 1) * 32);
        float4 r2 = *(const float4*)(xb + (4 * nb + 2) * 32);
        float4 r3 = *(const float4*)(xb + (4 * nb + 3) * 32);
        float* qb = &sm[OFF_QT + (32 * h + 4 * db) * LDN + SW(4 * nb)];
        *(float4*)(qb + 0 * LDN) = make_float4(r0.x*SCALE_F, r1.x*SCALE_F, r2.x*SCALE_F, r3.x*SCALE_F);
        *(float4*)(qb + 1 * LDN) = make_float4(r0.y*SCALE_F, r1.y*SCALE_F, r2.y*SCALE_F, r3.y*SCALE_F);
        *(float4*)(qb + 2 * LDN) = make_float4(r0.z*SCALE_F, r1.z*SCALE_F, r2.z*SCALE_F, r3.z*SCALE_F);
        *(float4*)(qb + 3 * LDN) = make_float4(r0.w*SCALE_F, r1.w*SCALE_F, r2.w*SCALE_F, r3.w*SCALE_F);
    }
    {
        const int nb = tid & 15, kb = tid >> 4;       // kb 0..31
        const float* yb = y + (size_t)b * 8192 + kb * 4;
        float4 r0 = *(const float4*)(yb + (4 * nb + 0) * 128);
        float4 r1 = *(const float4*)(yb + (4 * nb + 1) * 128);
        float4 r2 = *(const float4*)(yb + (4 * nb + 2) * 128);
        float4 r3 = *(const float4*)(yb + (4 * nb + 3) * 128);
        float* yt = &sm[OFF_AT + (4 * kb) * LDN + SW(4 * nb)];
        *(float4*)(yt + 0 * LDN) = make_float4(r0.x, r1.x, r2.x, r3.x);
        *(float4*)(yt + 1 * LDN) = make_float4(r0.y, r1.y, r2.y, r3.y);
        *(float4*)(yt + 2 * LDN) = make_float4(r0.z, r1.z, r2.z, r3.z);
        *(float4*)(yt + 3 * LDN) = make_float4(r0.w, r1.w, r2.w, r3.w);
    }

    // ===== GEMM1: kv[n][c] = sum_k y_t[k][n]*qkv_w[c][k] + qkv_b[c] =====
    // 2-way split-k (g = tid>>8, k-range g*64..+64), 8n x 8c tiles.
    // Unified dest: OFF_KT + c*LDN covers k_t (c<128) and v_t (c>=128).
    {
        const int g = tid >> 8, gtid = tid & 255;
        const int tc = gtid >> 3, tr = gtid & 7;
        const int c0 = tc << 3, r0 = tr << 3, r0s = SW(r0);
        const int WB = OFF_W + g * (16 * LDW);
        const int barid = 1 + g;
        const float* wsrc = qkv_w + gtid * 128 + (g << 6);

        u64 acc[4][8];
        #pragma unroll
        for (int p = 0; p < 4; ++p)
            #pragma unroll
            for (int cc = 0; cc < 8; ++cc) acc[p][cc] = 0ull;

        {   // stage chunk 0 (column gtid, 16 k values)
            float4 pw0 = *(const float4*)(wsrc);
            float4 pw1 = *(const float4*)(wsrc + 4);
            float4 pw2 = *(const float4*)(wsrc + 8);
            float4 pw3 = *(const float4*)(wsrc + 12);
            float wv[16] = {pw0.x,pw0.y,pw0.z,pw0.w, pw1.x,pw1.y,pw1.z,pw1.w,
                            pw2.x,pw2.y,pw2.z,pw2.w, pw3.x,pw3.y,pw3.z,pw3.w};
            #pragma unroll
            for (int jj = 0; jj < 16; ++jj)
                sm[WB + jj * LDW + gtid] = wv[jj];
        }
        __syncthreads();   // transposes + both groups' W chunk0 visible

        #pragma unroll 1
        for (int ch = 0; ch < 4; ++ch) {
            const int krow = (g << 6) + (ch << 4);
            float4 pw0, pw1, pw2, pw3;
            if (ch < 3) {
                const float* ws = wsrc + ((ch + 1) << 4);
                pw0 = *(const float4*)(ws);
                pw1 = *(const float4*)(ws + 4);
                pw2 = *(const float4*)(ws + 8);
                pw3 = *(const float4*)(ws + 12);
            }
            #pragma unroll 8
            for (int j = 0; j < 16; ++j) {
                const float* ar = &sm[OFF_AT + (krow + j) * LDN + r0s];
                float4 af0 = *(const float4*)ar;
                float4 af1 = *(const float4*)(ar + 4);
                u64 a0 = pkab(af0.x, af0.y), a1 = pkab(af0.z, af0.w);
                u64 a2 = pkab(af1.x, af1.y), a3 = pkab(af1.z, af1.w);
                const float* br = &sm[WB + j * LDW + c0];
                float4 bv0 = *(const float4*)br;
                float4 bv1 = *(const float4*)(br + 4);
                float bs[8] = {bv0.x,bv0.y,bv0.z,bv0.w, bv1.x,bv1.y,bv1.z,bv1.w};
                #pragma unroll
                for (int cc = 0; cc < 8; ++cc) {
                    u64 bb = pk2(bs[cc]);
                    acc[0][cc] = f2fma(a0, bb, acc[0][cc]);
                    acc[1][cc] = f2fma(a1, bb, acc[1][cc]);
                    acc[2][cc] = f2fma(a2, bb, acc[2][cc]);
                    acc[3][cc] = f2fma(a3, bb, acc[3][cc]);
                }
            }
            if (ch < 3) {
                gbar(barid);
                float wv[16] = {pw0.x,pw0.y,pw0.z,pw0.w, pw1.x,pw1.y,pw1.z,pw1.w,
                                pw2.x,pw2.y,pw2.z,pw2.w, pw3.x,pw3.y,pw3.z,pw3.w};
                #pragma unroll
                for (int jj = 0; jj < 16; ++jj)
                    sm[WB + jj * LDW + gtid] = wv[jj];
                gbar(barid);
            }
        }

        // g0: raw partial -> dest; sync; g1: add partial + bias -> dest
        if (g == 0) {
            #pragma unroll
            for (int cc = 0; cc < 8; ++cc) {
                float* dp = &sm[OFF_KT + (c0 + cc) * LDN + r0s];
                #pragma unroll
                for (int p = 0; p < 4; ++p)
                    *(u64*)(dp + 2 * p) = acc[p][cc];
            }
        }
        __syncthreads();
        if (g == 1) {
            float bias[8];
            *(float4*)&bias[0] = *(const float4*)(qkv_b + c0);
            *(float4*)&bias[4] = *(const float4*)(qkv_b + c0 + 4);
            #pragma unroll
            for (int cc = 0; cc < 8; ++cc) {
                float* dp = &sm[OFF_KT + (c0 + cc) * LDN + r0s];
                u64 bb = pk2(bias[cc]);
                #pragma unroll
                for (int p = 0; p < 4; ++p) {
                    u64 part = lds2(dp + 2 * p);
                    *(u64*)(dp + 2 * p) = f2add(f2add(acc[p][cc], part), bb);
                }
            }
        }
    }
    __syncthreads();

    // ===== GEMM2: attn_t[h*64+m][n] = sum_d q_t[32h+d][n]*k_t[32h+d][m] =====
    {
        const int h = tid >> 7, rest = tid & 127;
        const int mg = rest >> 3, tr = rest & 7;
        const int m0 = mg << 2, r0 = tr << 3;
        const int r0s = SW(r0), m0s = SW(m0);
        u64 acc[4][4];
        #pragma unroll
        for (int p = 0; p < 4; ++p)
            #pragma unroll
            for (int cc = 0; cc < 4; ++cc) acc[p][cc] = 0ull;
        #pragma unroll 8
        for (int d = 0; d < 32; ++d) {
            const int row = (h << 5) + d;
            const float* ar = &sm[OFF_QT + row * LDN + r0s];
            float4 af0 = *(const float4*)ar;
            float4 af1 = *(const float4*)(ar + 4);
            u64 a0 = pkab(af0.x, af0.y), a1 = pkab(af0.z, af0.w);
            u64 a2 = pkab(af1.x, af1.y), a3 = pkab(af1.z, af1.w);
            float4 bv = *(const float4*)&sm[OFF_KT + row * LDN + m0s];
            float bs[4] = {bv.x, bv.y, bv.z, bv.w};
            #pragma unroll
            for (int cc = 0; cc < 4; ++cc) {
                u64 bb = pk2(bs[cc]);
                acc[0][cc] = f2fma(a0, bb, acc[0][cc]);
                acc[1][cc] = f2fma(a1, bb, acc[1][cc]);
                acc[2][cc] = f2fma(a2, bb, acc[2][cc]);
                acc[3][cc] = f2fma(a3, bb, acc[3][cc]);
            }
        }
        #pragma unroll
        for (int cc = 0; cc < 4; ++cc) {
            const int row = (h << 6) + m0 + cc;
            #pragma unroll
            for (int p = 0; p < 4; ++p)
                *(u64*)&sm[OFF_AT + row * LDN + r0s + 2 * p] = acc[p][cc];
        }
    }
    __syncthreads();

    // ===== Softmax over m with mask + lambda*P; 2 threads per column =====
    {
        const int col = tid & 255, half = tid >> 8;
        const int h = col >> 6, n = col & 63;
        const int m0 = half << 5;
        const int ns = SW(n);
        const float lam = lam_p[0];
        const int w = b & 2047;
        const float4* Pr = (const float4*)(P + ((((size_t)b * 4 + h) * 64 + n) * 64) + m0);
        const float4* Mr = (const float4*)(maskp + (((size_t)w * 64 + n) * 64) + m0);
        const int base = OFF_AT + ((h << 6) + m0) * LDN + ns;
        float v[32];
        float s = 0.f;
        #pragma unroll
        for (int q = 0; q < 8; ++q) {
            float4 pv = Pr[q];
            float4 mv = Mr[q];
            float t0 = sm[base + (4*q+0)*LDN] + mv.x + lam * pv.x;
            float t1 = sm[base + (4*q+1)*LDN] + mv.y + lam * pv.y;
            float t2 = sm[base + (4*q+2)*LDN] + mv.z + lam * pv.z;
            float t3 = sm[base + (4*q+3)*LDN] + mv.w + lam * pv.w;
            v[4*q+0] = __expf(t0); v[4*q+1] = __expf(t1);
            v[4*q+2] = __expf(t2); v[4*q+3] = __expf(t3);
            s += v[4*q+0] + v[4*q+1] + v[4*q+2] + v[4*q+3];
        }
        sm[OFF_SC + (half << 8) + col] = s;
        __syncthreads();
        const float inv = 1.0f / (sm[OFF_SC + col] + sm[OFF_SC + 256 + col]);
        #pragma unroll
        for (int m = 0; m < 32; ++m) sm[base + m * LDN] = v[m] * inv;
    }
    __syncthreads();

    // ===== GEMM3: o_t[j][n] = sum_m attn_t[h*64+m][n] * v_t[j][m], h=j/32 =====
    {
        const int nr = tid & 15, jc = tid >> 4;
        const int n0 = nr << 2, j0 = jc << 2, h = jc >> 3;
        const int n0s = SW(n0);
        u64 acc[2][4];
        #pragma unroll
        for (int p = 0; p < 2; ++p)
            #pragma unroll
            for (int cc = 0; cc < 4; ++cc) acc[p][cc] = 0ull;
        #pragma unroll 16
        for (int m = 0; m < 64; ++m) {
            const int ms = SW(m);
            float4 af = *(const float4*)&sm[OFF_AT + ((h << 6) + m) * LDN + n0s];
            u64 a0 = pkab(af.x, af.y), a1 = pkab(af.z, af.w);
            #pragma unroll
            for (int cc = 0; cc < 4; ++cc) {
                u64 bb = pk2(sm[OFF_V + (j0 + cc) * LDN + ms]);
                acc[0][cc] = f2fma(a0, bb, acc[0][cc]);
                acc[1][cc] = f2fma(a1, bb, acc[1][cc]);
            }
        }
        #pragma unroll
        for (int cc = 0; cc < 4; ++cc)
            #pragma unroll
            for (int p = 0; p < 2; ++p)
                *(u64*)&sm[OFF_QT + (j0 + cc) * LDN + n0s + 2 * p] = acc[p][cc];
    }
    __syncthreads();

    // ===== Stage proj_w transposed: p_t[j][c] (aliases dead attn region) =====
    {
        const int c = tid >> 2, qq = tid & 3;
        const float* pr = proj_w + c * 128 + qq * 32;
        #pragma unroll
        for (int i = 0; i < 8; ++i) {
            float4 pv = ((const float4*)pr)[i];
            const int j = (qq << 5) + (i << 2);
            sm[OFF_AT + (j    ) * LDP + c] = pv.x;
            sm[OFF_AT + (j + 1) * LDP + c] = pv.y;
            sm[OFF_AT + (j + 2) * LDP + c] = pv.z;
            sm[OFF_AT + (j + 3) * LDP + c] = pv.w;
        }
    }
    __syncthreads();

    // ===== GEMM4: res[n][c] = sum_j o_t[j][n]*p_t[j][c] + proj_b[c] =====
    // 2-way split-j (g = tid>>8, j-range g*64..+64), 8n x 4c tiles.
    {
        const int g = tid >> 8, gtid = tid & 255;
        const int tr = gtid & 7, tc = gtid >> 3;
        const int n0 = tr << 3, n0s = SW(n0), c0 = tc << 2;
        const int jbase = g << 6;
        u64 acc[4][4];
        #pragma unroll
        for (int p = 0; p < 4; ++p)
            #pragma unroll
            for (int cc = 0; cc < 4; ++cc) acc[p][cc] = 0ull;
        #pragma unroll 8
        for (int jj = 0; jj < 64; ++jj) {
            const float* ar = &sm[OFF_QT + (jbase + jj) * LDN + n0s];
            float4 af0 = *(const float4*)ar;
            float4 af1 = *(const float4*)(ar + 4);
            u64 a0 = pkab(af0.x, af0.y), a1 = pkab(af0.z, af0.w);
            u64 a2 = pkab(af1.x, af1.y), a3 = pkab(af1.z, af1.w);
            float4 bv = *(const float4*)&sm[OFF_AT + (jbase + jj) * LDP + c0];
            float bs[4] = {bv.x, bv.y, bv.z, bv.w};
            #pragma unroll
            for (int cc = 0; cc < 4; ++cc) {
                u64 bb = pk2(bs[cc]);
                acc[0][cc] = f2fma(a0, bb, acc[0][cc]);
                acc[1][cc] = f2fma(a1, bb, acc[1][cc]);
                acc[2][cc] = f2fma(a2, bb, acc[2][cc]);
                acc[3][cc] = f2fma(a3, bb, acc[3][cc]);
            }
        }
        // g1: partial -> scratch (dead k_t region), same [c][n] layout
        if (g == 1) {
            #pragma unroll
            for (int cc = 0; cc < 4; ++cc) {
                float* dp = &sm[OFF_KT + (c0 + cc) * LDN + n0s];
                #pragma unroll
                for (int p = 0; p < 4; ++p)
                    *(u64*)(dp + 2 * p) = acc[p][cc];
            }
        }
        __syncthreads();
        if (g == 0) {
            float4 pb = *(const float4*)(proj_b + c0);
            float bias[4] = {pb.x, pb.y, pb.z, pb.w};
            float* ob = out + (size_t)b * 8192;
            #pragma unroll
            for (int p = 0; p < 4; ++p) {
                float lo[4], hi[4];
                #pragma unroll
                for (int cc = 0; cc < 4; ++cc) {
                    u64 part = lds2(&sm[OFF_KT + (c0 + cc) * LDN + n0s + 2 * p]);
                    u64 sum = f2add(acc[p][cc], part);
                    float l, h0; upk2(sum, l, h0);
                    lo[cc] = l + bias[cc];
                    hi[cc] = h0 + bias[cc];
                }
                *(float4*)&ob[(n0 + 2*p    ) * 128 + c0] = make_float4(lo[0], lo[1], lo[2], lo[3]);
                *(float4*)&ob[(n0 + 2*p + 1) * 128 + c0] = make_float4(hi[0], hi[1], hi[2], hi[3]);
            }
        }
    }
}

extern "C" void kernel_launch(void* const* d_in, const int* in_sizes, int n_in,
                              void* d_out, int out_size)
{
    const float* x      = (const float*)d_in[0];
    const float* y      = (const float*)d_in[1];
    const float* P      = (const float*)d_in[2];
    const float* maskp  = (const float*)d_in[3];
    const float* qkv_w  = (const float*)d_in[4];
    const float* qkv_b  = (const float*)d_in[5];
    const float* proj_w = (const float*)d_in[6];
    const float* proj_b = (const float*)d_in[7];
    const float* lam    = (const float*)d_in[8];
    float* out = (float*)d_out;

    cudaFuncSetAttribute(wattn_kernel,
                         cudaFuncAttributeMaxDynamicSharedMemorySize, SMEM_BYTES);
    wattn_kernel<<<4096, 512, SMEM_BYTES>>>(x, y, P, maskp, qkv_w, qkv_b,
                                            proj_w, proj_b, lam, out);
}

// round 15
// speedup vs baseline: 1.7746x; 1.0759x over previous
#include <cuda_runtime.h>
#include <cuda_bf16.h>
#include <mma.h>
#include <cstdint>

// WindowAttention fused kernel (sm_103a host, plain sm_103 PTX target).
// R14: GEMM1 (kv projection) on HMMA via nvcuda::wmma bf16 m16n16k16, 3-pass
//      bf16-split (Ah*Bh + Ah*Bl + Al*Bh, f32 accum). Output stored directly
//      into swizzled k_t/v_t. GEMM2/3/4 + softmax unchanged from R11.

using namespace nvcuda;

#define SCALE_F 0.17677669529663687f   // 32^-0.5

#define LDN 68
#define LDP 132
#define SW(c) ((c) + (((c) & 32) >> 3))

#define OFF_KT 0                       // k_t [128][LDN] (-> GEMM4 scratch later)
#define OFF_V  (128*LDN)               // v_t [128][LDN] (contiguous with k_t)
#define OFF_QT (2*128*LDN)             // q_t [128][LDN] -> o_t after GEMM3
#define OFF_AT (3*128*LDN)             // attn_t [256][LDN] -> p_t [128][LDP]
#define OFF_SC (OFF_AT + 256*LDN)      // softmax scratch [2][256]
#define SMEM_FLOATS (OFF_SC + 512)
#define SMEM_BYTES  (SMEM_FLOATS * 4)  // 176128 B

// bf16 staging (byte offsets, overlap dead QT/AT regions: 69632..174080)
#define LDKB 136                       // bf16 leading dim (k), 272B rows
#define WH_B 69632                     // W-half hi  [128][LDKB] = 34816 B
#define WL_B 104448                    // W-half lo
#define YH_B 139264                    // Y hi [64][LDKB] = 17408 B
#define YL_B 156672                    // Y lo            (ends 174080)

typedef unsigned long long u64;

__device__ __forceinline__ u64 pk2(float v) {
    u64 r; asm("mov.b64 %0, {%1, %1};" : "=l"(r) : "f"(v)); return r;
}
__device__ __forceinline__ u64 pkab(float lo, float hi) {
    u64 r; asm("mov.b64 %0, {%1, %2};" : "=l"(r) : "f"(lo), "f"(hi)); return r;
}
__device__ __forceinline__ u64 f2fma(u64 a, u64 b, u64 c) {
    u64 d; asm("fma.rn.f32x2 %0, %1, %2, %3;" : "=l"(d) : "l"(a), "l"(b), "l"(c)); return d;
}
__device__ __forceinline__ u64 f2add(u64 a, u64 b) {
    u64 d; asm("add.rn.f32x2 %0, %1, %2;" : "=l"(d) : "l"(a), "l"(b)); return d;
}
__device__ __forceinline__ void upk2(u64 v, float& lo, float& hi) {
    asm("mov.b64 {%0, %1}, %2;" : "=f"(lo), "=f"(hi) : "l"(v));
}
__device__ __forceinline__ u64 lds2(const float* p) {
    return *reinterpret_cast<const u64*>(p);
}
__device__ __forceinline__ unsigned short f2bf(float f) {
    return __bfloat16_as_ushort(__float2bfloat16(f));
}
__device__ __forceinline__ float bf2f(unsigned short u) {
    return __bfloat162float(__ushort_as_bfloat16(u));
}
// 8 consecutive floats -> packed bf16 hi (16B) + residual lo (16B)
__device__ __forceinline__ void cvt8(const float* f, uint4& H, uint4& L) {
    unsigned int h[4], l[4];
    #pragma unroll
    for (int i = 0; i < 4; ++i) {
        float a = f[2*i], c = f[2*i+1];
        unsigned short ha = f2bf(a), hc = f2bf(c);
        float ra = a - bf2f(ha), rc = c - bf2f(hc);
        unsigned short la = f2bf(ra), lc = f2bf(rc);
        h[i] = (unsigned)ha | ((unsigned)hc << 16);
        l[i] = (unsigned)la | ((unsigned)lc << 16);
    }
    H = make_uint4(h[0], h[1], h[2], h[3]);
    L = make_uint4(l[0], l[1], l[2], l[3]);
}

__global__ void __launch_bounds__(512, 1)
wattn_kernel(const float* __restrict__ x, const float* __restrict__ y,
             const float* __restrict__ P, const float* __restrict__ maskp,
             const float* __restrict__ qkv_w, const float* __restrict__ qkv_b,
             const float* __restrict__ proj_w, const float* __restrict__ proj_b,
             const float* __restrict__ lam_p, float* __restrict__ out)
{
    extern __shared__ float sm[];
    char* smc = reinterpret_cast<char*>(sm);
    const int b   = blockIdx.x;
    const int tid = threadIdx.x;
    const int wid = tid >> 5;

    __nv_bfloat16* wh = (__nv_bfloat16*)(smc + WH_B);
    __nv_bfloat16* wl = (__nv_bfloat16*)(smc + WL_B);
    __nv_bfloat16* yh = (__nv_bfloat16*)(smc + YH_B);
    __nv_bfloat16* yl = (__nv_bfloat16*)(smc + YL_B);

    // ---- prefetch x into registers (q_t staged after GEMM1) ----
    float4 xr0, xr1, xr2, xr3;
    const int xh = tid >> 7, xnb = (tid >> 3) & 15, xdb = tid & 7;
    {
        const float* xb = x + (size_t)b * 8192 + xh * 2048 + xdb * 4;
        xr0 = *(const float4*)(xb + (4 * xnb + 0) * 32);
        xr1 = *(const float4*)(xb + (4 * xnb + 1) * 32);
        xr2 = *(const float4*)(xb + (4 * xnb + 2) * 32);
        xr3 = *(const float4*)(xb + (4 * xnb + 3) * 32);
    }

    // ---- stage Y -> bf16 hi/lo [64][LDKB] ----
    {
        const int n = tid >> 3, k0 = (tid & 7) << 4;
        const float* yr = y + (size_t)b * 8192 + n * 128 + k0;
        float f[16];
        *(float4*)&f[0]  = *(const float4*)(yr);
        *(float4*)&f[4]  = *(const float4*)(yr + 4);
        *(float4*)&f[8]  = *(const float4*)(yr + 8);
        *(float4*)&f[12] = *(const float4*)(yr + 12);
        #pragma unroll
        for (int u = 0; u < 2; ++u) {
            uint4 H, L; cvt8(&f[8 * u], H, L);
            *(uint4*)(yh + n * LDKB + k0 + 8 * u) = H;
            *(uint4*)(yl + n * LDKB + k0 + 8 * u) = L;
        }
    }
    // ---- stage W half 0 (rows 0..127) -> bf16 hi/lo [128][LDKB] ----
    {
        const int r = tid >> 2, k0 = (tid & 3) << 5;
        const float* wr = qkv_w + r * 128 + k0;
        float f[32];
        #pragma unroll
        for (int i = 0; i < 8; ++i) *(float4*)&f[4 * i] = *(const float4*)(wr + 4 * i);
        #pragma unroll
        for (int u = 0; u < 4; ++u) {
            uint4 H, L; cvt8(&f[8 * u], H, L);
            *(uint4*)(wh + r * LDKB + k0 + 8 * u) = H;
            *(uint4*)(wl + r * LDKB + k0 + 8 * u) = L;
        }
    }
    __syncthreads();

    // ---- wmma half 0: D[c][n] = sum_k W[c][k]*y[n][k], c 0..127 -> k_t ----
    {
        const int c0 = (wid >> 1) << 4;
        const int n0a = (wid & 1) << 5, n0b = n0a + 16;
        const int nas = n0a + ((n0a & 32) >> 3), nbs = n0b + ((n0b & 32) >> 3);
        wmma::fragment<wmma::accumulator, 16, 16, 16, float> acc0, acc1;
        wmma::fill_fragment(acc0, 0.0f);
        wmma::fill_fragment(acc1, 0.0f);
        #pragma unroll
        for (int k0 = 0; k0 < 128; k0 += 16) {
            wmma::fragment<wmma::matrix_a, 16, 16, 16, __nv_bfloat16, wmma::row_major> Ah, Al;
            wmma::load_matrix_sync(Ah, wh + c0 * LDKB + k0, LDKB);
            wmma::load_matrix_sync(Al, wl + c0 * LDKB + k0, LDKB);
            wmma::fragment<wmma::matrix_b, 16, 16, 16, __nv_bfloat16, wmma::col_major> Bh, Bl;
            wmma::load_matrix_sync(Bh, yh + n0a * LDKB + k0, LDKB);
            wmma::load_matrix_sync(Bl, yl + n0a * LDKB + k0, LDKB);
            wmma::mma_sync(acc0, Ah, Bh, acc0);
            wmma::mma_sync(acc0, Ah, Bl, acc0);
            wmma::mma_sync(acc0, Al, Bh, acc0);
            wmma::load_matrix_sync(Bh, yh + n0b * LDKB + k0, LDKB);
            wmma::load_matrix_sync(Bl, yl + n0b * LDKB + k0, LDKB);
            wmma::mma_sync(acc1, Ah, Bh, acc1);
            wmma::mma_sync(acc1, Ah, Bl, acc1);
            wmma::mma_sync(acc1, Al, Bh, acc1);
        }
        wmma::store_matrix_sync(&sm[OFF_KT + c0 * LDN + nas], acc0, LDN, wmma::mem_row_major);
        wmma::store_matrix_sync(&sm[OFF_KT + c0 * LDN + nbs], acc1, LDN, wmma::mem_row_major);
    }
    __syncthreads();

    // ---- stage W half 1 (rows 128..255) into the same buffers ----
    {
        const int r = tid >> 2, k0 = (tid & 3) << 5;
        const float* wr = qkv_w + (128 + r) * 128 + k0;
        float f[32];
        #pragma unroll
        for (int i = 0; i < 8; ++i) *(float4*)&f[4 * i] = *(const float4*)(wr + 4 * i);
        #pragma unroll
        for (int u = 0; u < 4; ++u) {
            uint4 H, L; cvt8(&f[8 * u], H, L);
            *(uint4*)(wh + r * LDKB + k0 + 8 * u) = H;
            *(uint4*)(wl + r * LDKB + k0 + 8 * u) = L;
        }
    }
    __syncthreads();

    // ---- wmma half 1: c 128..255 -> v_t ----
    {
        const int c0 = (wid >> 1) << 4;
        const int n0a = (wid & 1) << 5, n0b = n0a + 16;
        const int nas = n0a + ((n0a & 32) >> 3), nbs = n0b + ((n0b & 32) >> 3);
        wmma::fragment<wmma::accumulator, 16, 16, 16, float> acc0, acc1;
        wmma::fill_fragment(acc0, 0.0f);
        wmma::fill_fragment(acc1, 0.0f);
        #pragma unroll
        for (int k0 = 0; k0 < 128; k0 += 16) {
            wmma::fragment<wmma::matrix_a, 16, 16, 16, __nv_bfloat16, wmma::row_major> Ah, Al;
            wmma::load_matrix_sync(Ah, wh + c0 * LDKB + k0, LDKB);
            wmma::load_matrix_sync(Al, wl + c0 * LDKB + k0, LDKB);
            wmma::fragment<wmma::matrix_b, 16, 16, 16, __nv_bfloat16, wmma::col_major> Bh, Bl;
            wmma::load_matrix_sync(Bh, yh + n0a * LDKB + k0, LDKB);
            wmma::load_matrix_sync(Bl, yl + n0a * LDKB + k0, LDKB);
            wmma::mma_sync(acc0, Ah, Bh, acc0);
            wmma::mma_sync(acc0, Ah, Bl, acc0);
            wmma::mma_sync(acc0, Al, Bh, acc0);
            wmma::load_matrix_sync(Bh, yh + n0b * LDKB + k0, LDKB);
            wmma::load_matrix_sync(Bl, yl + n0b * LDKB + k0, LDKB);
            wmma::mma_sync(acc1, Ah, Bh, acc1);
            wmma::mma_sync(acc1, Ah, Bl, acc1);
            wmma::mma_sync(acc1, Al, Bh, acc1);
        }
        wmma::store_matrix_sync(&sm[OFF_V + c0 * LDN + nas], acc0, LDN, wmma::mem_row_major);
        wmma::store_matrix_sync(&sm[OFF_V + c0 * LDN + nbs], acc1, LDN, wmma::mem_row_major);
    }
    __syncthreads();

    // ---- bias fixup for k_t/v_t (contiguous 256 rows) + stage q_t ----
    {
        const int c2 = tid >> 1;                 // 0..255 row of k_t|v_t
        const int off = (tid & 1) * 36;          // cols 0..31 at +0, 32..63 at +36
        const float bias = qkv_b[c2];
        u64 bb = pk2(bias);
        float* dp = &sm[OFF_KT + c2 * LDN + off];
        #pragma unroll
        for (int i = 0; i < 16; ++i)
            *(u64*)(dp + 2 * i) = f2add(lds2(dp + 2 * i), bb);
    }
    {
        float* qb = &sm[OFF_QT + (32 * xh + 4 * xdb) * LDN + SW(4 * xnb)];
        *(float4*)(qb + 0 * LDN) = make_float4(xr0.x*SCALE_F, xr1.x*SCALE_F, xr2.x*SCALE_F, xr3.x*SCALE_F);
        *(float4*)(qb + 1 * LDN) = make_float4(xr0.y*SCALE_F, xr1.y*SCALE_F, xr2.y*SCALE_F, xr3.y*SCALE_F);
        *(float4*)(qb + 2 * LDN) = make_float4(xr0.z*SCALE_F, xr1.z*SCALE_F, xr2.z*SCALE_F, xr3.z*SCALE_F);
        *(float4*)(qb + 3 * LDN) = make_float4(xr0.w*SCALE_F, xr1.w*SCALE_F, xr2.w*SCALE_F, xr3.w*SCALE_F);
    }
    __syncthreads();

    // ===== GEMM2: attn_t[h*64+m][n] = sum_d q_t[32h+d][n]*k_t[32h+d][m] =====
    {
        const int h = tid >> 7, rest = tid & 127;
        const int mg = rest >> 3, tr = rest & 7;
        const int m0 = mg << 2, r0 = tr << 3;
        const int r0s = SW(r0), m0s = SW(m0);
        u64 acc[4][4];
        #pragma unroll
        for (int p = 0; p < 4; ++p)
            #pragma unroll
            for (int cc = 0; cc < 4; ++cc) acc[p][cc] = 0ull;
        #pragma unroll 8
        for (int d = 0; d < 32; ++d) {
            const int row = (h << 5) + d;
            const float* ar = &sm[OFF_QT + row * LDN + r0s];
            float4 af0 = *(const float4*)ar;
            float4 af1 = *(const float4*)(ar + 4);
            u64 a0 = pkab(af0.x, af0.y), a1 = pkab(af0.z, af0.w);
            u64 a2 = pkab(af1.x, af1.y), a3 = pkab(af1.z, af1.w);
            float4 bv = *(const float4*)&sm[OFF_KT + row * LDN + m0s];
            float bs[4] = {bv.x, bv.y, bv.z, bv.w};
            #pragma unroll
            for (int cc = 0; cc < 4; ++cc) {
                u64 bb = pk2(bs[cc]);
                acc[0][cc] = f2fma(a0, bb, acc[0][cc]);
                acc[1][cc] = f2fma(a1, bb, acc[1][cc]);
                acc[2][cc] = f2fma(a2, bb, acc[2][cc]);
                acc[3][cc] = f2fma(a3, bb, acc[3][cc]);
            }
        }
        #pragma unroll
        for (int cc = 0; cc < 4; ++cc) {
            const int row = (h << 6) + m0 + cc;
            #pragma unroll
            for (int p = 0; p < 4; ++p)
                *(u64*)&sm[OFF_AT + row * LDN + r0s + 2 * p] = acc[p][cc];
        }
    }
    __syncthreads();

    // ===== Softmax over m with mask + lambda*P; 2 threads per column =====
    {
        const int col = tid & 255, half = tid >> 8;
        const int h = col >> 6, n = col & 63;
        const int m0 = half << 5;
        const int ns = SW(n);
        const float lam = lam_p[0];
        const int w = b & 2047;
        const float4* Pr = (const float4*)(P + ((((size_t)b * 4 + h) * 64 + n) * 64) + m0);
        const float4* Mr = (const float4*)(maskp + (((size_t)w * 64 + n) * 64) + m0);
        const int base = OFF_AT + ((h << 6) + m0) * LDN + ns;
        float v[32];
        float s = 0.f;
        #pragma unroll
        for (int q = 0; q < 8; ++q) {
            float4 pv = Pr[q];
            float4 mv = Mr[q];
            float t0 = sm[base + (4*q+0)*LDN] + mv.x + lam * pv.x;
            float t1 = sm[base + (4*q+1)*LDN] + mv.y + lam * pv.y;
            float t2 = sm[base + (4*q+2)*LDN] + mv.z + lam * pv.z;
            float t3 = sm[base + (4*q+3)*LDN] + mv.w + lam * pv.w;
            v[4*q+0] = __expf(t0); v[4*q+1] = __expf(t1);
            v[4*q+2] = __expf(t2); v[4*q+3] = __expf(t3);
            s += v[4*q+0] + v[4*q+1] + v[4*q+2] + v[4*q+3];
        }
        sm[OFF_SC + (half << 8) + col] = s;
        __syncthreads();
        const float inv = 1.0f / (sm[OFF_SC + col] + sm[OFF_SC + 256 + col]);
        #pragma unroll
        for (int m = 0; m < 32; ++m) sm[base + m * LDN] = v[m] * inv;
    }
    __syncthreads();

    // ===== GEMM3: o_t[j][n] = sum_m attn_t[h*64+m][n] * v_t[j][m], h=j/32 =====
    {
        const int nr = tid & 15, jc = tid >> 4;
        const int n0 = nr << 2, j0 = jc << 2, h = jc >> 3;
        const int n0s = SW(n0);
        u64 acc[2][4];
        #pragma unroll
        for (int p = 0; p < 2; ++p)
            #pragma unroll
            for (int cc = 0; cc < 4; ++cc) acc[p][cc] = 0ull;
        #pragma unroll 16
        for (int m = 0; m < 64; ++m) {
            const int ms = SW(m);
            float4 af = *(const float4*)&sm[OFF_AT + ((h << 6) + m) * LDN + n0s];
            u64 a0 = pkab(af.x, af.y), a1 = pkab(af.z, af.w);
            #pragma unroll
            for (int cc = 0; cc < 4; ++cc) {
                u64 bb = pk2(sm[OFF_V + (j0 + cc) * LDN + ms]);
                acc[0][cc] = f2fma(a0, bb, acc[0][cc]);
                acc[1][cc] = f2fma(a1, bb, acc[1][cc]);
            }
        }
        #pragma unroll
        for (int cc = 0; cc < 4; ++cc)
            #pragma unroll
            for (int p = 0; p < 2; ++p)
                *(u64*)&sm[OFF_QT + (j0 + cc) * LDN + n0s + 2 * p] = acc[p][cc];
    }
    __syncthreads();

    // ===== Stage proj_w transposed: p_t[j][c] (aliases dead attn region) =====
    {
        const int c = tid >> 2, qq = tid & 3;
        const float* pr = proj_w + c * 128 + qq * 32;
        #pragma unroll
        for (int i = 0; i < 8; ++i) {
            float4 pv = ((const float4*)pr)[i];
            const int j = (qq << 5) + (i << 2);
            sm[OFF_AT + (j    ) * LDP + c] = pv.x;
            sm[OFF_AT + (j + 1) * LDP + c] = pv.y;
            sm[OFF_AT + (j + 2) * LDP + c] = pv.z;
            sm[OFF_AT + (j + 3) * LDP + c] = pv.w;
        }
    }
    __syncthreads();

    // ===== GEMM4: res[n][c] = sum_j o_t[j][n]*p_t[j][c] + proj_b[c] =====
    // 2-way split-j (g = tid>>8), 8n x 4c tiles; g1 partials in dead k_t region.
    {
        const int g = tid >> 8, gtid = tid & 255;
        const int tr = gtid & 7, tc = gtid >> 3;
        const int n0 = tr << 3, n0s = SW(n0), c0 = tc << 2;
        const int jbase = g << 6;
        u64 acc[4][4];
        #pragma unroll
        for (int p = 0; p < 4; ++p)
            #pragma unroll
            for (int cc = 0; cc < 4; ++cc) acc[p][cc] = 0ull;
        #pragma unroll 8
        for (int jj = 0; jj < 64; ++jj) {
            const float* ar = &sm[OFF_QT + (jbase + jj) * LDN + n0s];
            float4 af0 = *(const float4*)ar;
            float4 af1 = *(const float4*)(ar + 4);
            u64 a0 = pkab(af0.x, af0.y), a1 = pkab(af0.z, af0.w);
            u64 a2 = pkab(af1.x, af1.y), a3 = pkab(af1.z, af1.w);
            float4 bv = *(const float4*)&sm[OFF_AT + (jbase + jj) * LDP + c0];
            float bs[4] = {bv.x, bv.y, bv.z, bv.w};
            #pragma unroll
            for (int cc = 0; cc < 4; ++cc) {
                u64 bb = pk2(bs[cc]);
                acc[0][cc] = f2fma(a0, bb, acc[0][cc]);
                acc[1][cc] = f2fma(a1, bb, acc[1][cc]);
                acc[2][cc] = f2fma(a2, bb, acc[2][cc]);
                acc[3][cc] = f2fma(a3, bb, acc[3][cc]);
            }
        }
        if (g == 1) {
            #pragma unroll
            for (int cc = 0; cc < 4; ++cc) {
                float* dp = &sm[OFF_KT + (c0 + cc) * LDN + n0s];
                #pragma unroll
                for (int p = 0; p < 4; ++p)
                    *(u64*)(dp + 2 * p) = acc[p][cc];
            }
        }
        __syncthreads();
        if (g == 0) {
            float4 pb = *(const float4*)(proj_b + c0);
            float bias[4] = {pb.x, pb.y, pb.z, pb.w};
            float* ob = out + (size_t)b * 8192;
            #pragma unroll
            for (int p = 0; p < 4; ++p) {
                float lo[4], hi[4];
                #pragma unroll
                for (int cc = 0; cc < 4; ++cc) {
                    u64 part = lds2(&sm[OFF_KT + (c0 + cc) * LDN + n0s + 2 * p]);
                    u64 sum = f2add(acc[p][cc], part);
                    float l, h0; upk2(sum, l, h0);
                    lo[cc] = l + bias[cc];
                    hi[cc] = h0 + bias[cc];
                }
                *(float4*)&ob[(n0 + 2*p    ) * 128 + c0] = make_float4(lo[0], lo[1], lo[2], lo[3]);
                *(float4*)&ob[(n0 + 2*p + 1) * 128 + c0] = make_float4(hi[0], hi[1], hi[2], hi[3]);
            }
        }
    }
}

extern "C" void kernel_launch(void* const* d_in, const int* in_sizes, int n_in,
                              void* d_out, int out_size)
{
    const float* x      = (const float*)d_in[0];
    const float* y      = (const float*)d_in[1];
    const float* P      = (const float*)d_in[2];
    const float* maskp  = (const float*)d_in[3];
    const float* qkv_w  = (const float*)d_in[4];
    const float* qkv_b  = (const float*)d_in[5];
    const float* proj_w = (const float*)d_in[6];
    const float* proj_b = (const float*)d_in[7];
    const float* lam    = (const float*)d_in[8];
    float* out = (float*)d_out;

    cudaFuncSetAttribute(wattn_kernel,
                         cudaFuncAttributeMaxDynamicSharedMemorySize, SMEM_BYTES);
    wattn_kernel<<<4096, 512, SMEM_BYTES>>>(x, y, P, maskp, qkv_w, qkv_b,
                                            proj_w, proj_b, lam, out);
}